// round 14
// baseline (speedup 1.0000x reference)
#include <cuda_runtime.h>
#include <cuda_fp16.h>
#include <cstdint>

// SparseConv3d implicit GEMM, round 14.
// R13 (136.8us main): 16 warps/SM, tensor 53%, L1 61%, issue 27% -> barrier/latency bound.
// R14: M_TILE 256 with 8 warps, 2 CTAs/SM (same 16 warps/SM):
//      halves barrier count per unit work, halves W staging per row.
//      Inner MMA loop identical to R13 (warp tile m64 x n32).

#define M_TILE   256
#define CIN      64
#define COUT     64
#define K3       27
#define NTHREADS 256
#define NFEAT_MAX 200000

#define A_STRIDE 72   // halves; 144B row stride, conflict-free ldmatrix, 16B-aligned chunks
#define W_STRIDE 72

// dynamic smem layout (bytes): two stages of (A | W)
#define A_BYTES      (M_TILE * A_STRIDE * 2)     // 36864
#define W_BYTES      (CIN * W_STRIDE * 2)        // 9216
#define STAGE_BYTES  (A_BYTES + W_BYTES)         // 46080
#define SMEM_TOTAL   (2 * STAGE_BYTES)           // 92160

__device__ __half g_featH[(size_t)NFEAT_MAX * CIN];
__device__ __half g_wH[K3 * CIN * COUT];

__device__ __forceinline__ uint32_t smem_u32(const void* p) {
    return (uint32_t)__cvta_generic_to_shared(p);
}

// ---------------- pre-pass: fp32 -> fp16 ----------------
__global__ void convert_kernel(const float* __restrict__ feat,
                               const float* __restrict__ wgt,
                               int nfeat_elems, int nw_elems)
{
    const int nf4 = nfeat_elems >> 2;
    const int nw4 = nw_elems >> 2;
    for (int i = blockIdx.x * blockDim.x + threadIdx.x; i < nf4 + nw4;
         i += gridDim.x * blockDim.x) {
        if (i < nf4) {
            float4 v = ((const float4*)feat)[i];
            __half2 h0 = __floats2half2_rn(v.x, v.y);
            __half2 h1 = __floats2half2_rn(v.z, v.w);
            uint2 o; o.x = *(uint32_t*)&h0; o.y = *(uint32_t*)&h1;
            ((uint2*)g_featH)[i] = o;
        } else {
            int j = i - nf4;
            float4 v = ((const float4*)wgt)[j];
            __half2 h0 = __floats2half2_rn(v.x, v.y);
            __half2 h1 = __floats2half2_rn(v.z, v.w);
            uint2 o; o.x = *(uint32_t*)&h0; o.y = *(uint32_t*)&h1;
            ((uint2*)g_wH)[j] = o;
        }
    }
}

// ---------------- main kernel ----------------
__device__ __forceinline__ void issue_tile_copies(int k, char* smem, int bsel,
                                                  const int* __restrict__ indices,
                                                  int base, int M, int Nfeat, int t)
{
    __half* sA = (__half*)(smem + bsel * STAGE_BYTES);
    __half* sW = (__half*)(smem + bsel * STAGE_BYTES + A_BYTES);

    const int tr = t >> 3;          // 0..31
    const int tc = (t & 7) * 8;     // halves offset (16B chunk)

#pragma unroll
    for (int p = 0; p < 8; ++p) {
        int row  = tr + p * 32;
        int grow = base + row;
        int gi   = (grow < M) ? __ldg(indices + (long long)grow * K3 + k) : -1;
        if (gi < 0 || gi >= Nfeat) gi = -1;
        const __half* src = g_featH + (size_t)max(gi, 0) * CIN + tc;
        uint32_t dst = smem_u32(&sA[row * A_STRIDE + tc]);
        int sz = (gi >= 0) ? 16 : 0;
        asm volatile("cp.async.cg.shared.global [%0], [%1], 16, %2;\n"
                     :: "r"(dst), "l"(src), "r"(sz));
    }
#pragma unroll
    for (int p = 0; p < 2; ++p) {
        int row = tr + p * 32;
        const __half* src = g_wH + ((size_t)k * CIN + row) * COUT + tc;
        uint32_t dst = smem_u32(&sW[row * W_STRIDE + tc]);
        asm volatile("cp.async.cg.shared.global [%0], [%1], 16;\n"
                     :: "r"(dst), "l"(src));
    }
    asm volatile("cp.async.commit_group;\n" ::: "memory");
}

__global__ __launch_bounds__(NTHREADS, 2)
void spconv_mma_kernel(const int* __restrict__ indices,
                       float* __restrict__ out,
                       int M, int Nfeat)
{
    extern __shared__ char smem[];

    const int t    = threadIdx.x;
    const int warp = t >> 5;       // 0..7
    const int lane = t & 31;
    const int base = blockIdx.x * M_TILE;

    const int wm = warp >> 1;      // 0..3 -> m offset wm*64
    const int wn = warp & 1;       // 0..1 -> n offset wn*32

    // ---- prologue: stages 0 and 1 in flight ----
    issue_tile_copies(0, smem, 0, indices, base, M, Nfeat, t);
    issue_tile_copies(1, smem, 1, indices, base, M, Nfeat, t);

    // warp tile m64 x n32: acc[mt 0..3][n8-tile 0..3][4]
    float acc[4][4][4];
#pragma unroll
    for (int a = 0; a < 4; ++a)
#pragma unroll
        for (int b = 0; b < 4; ++b)
#pragma unroll
            for (int c = 0; c < 4; ++c) acc[a][b][c] = 0.f;

    for (int k = 0; k < K3; ++k) {
        const int bsel = k & 1;
        if (k == K3 - 1)
            asm volatile("cp.async.wait_group 0;\n" ::: "memory");
        else
            asm volatile("cp.async.wait_group 1;\n" ::: "memory");
        __syncthreads();   // stage k visible to all warps

        const uint32_t aB = smem_u32(smem + bsel * STAGE_BYTES);
        const uint32_t wB = aB + A_BYTES;

        // ---- warp tile m64 x n32 x k64 ----
#pragma unroll
        for (int ks = 0; ks < 4; ++ks) {
            uint32_t af[4][4];
#pragma unroll
            for (int mt = 0; mt < 4; ++mt) {
                int r = wm * 64 + mt * 16 + (lane & 15);
                int c = ks * 16 + ((lane >> 4) << 3);
                uint32_t addr = aB + (uint32_t)(r * A_STRIDE + c) * 2u;
                asm volatile("ldmatrix.sync.aligned.m8n8.x4.shared.b16 {%0,%1,%2,%3}, [%4];\n"
                             : "=r"(af[mt][0]), "=r"(af[mt][1]),
                               "=r"(af[mt][2]), "=r"(af[mt][3]) : "r"(addr));
            }
#pragma unroll
            for (int nt = 0; nt < 2; ++nt) {
                uint32_t b0, b1, b2, b3;
                {
                    int g    = lane >> 3;
                    int l8   = lane & 7;
                    int krow = ks * 16 + l8 + ((g & 1) << 3);
                    int ncol = wn * 32 + nt * 16 + ((g >> 1) << 3);
                    uint32_t addr = wB + (uint32_t)(krow * W_STRIDE + ncol) * 2u;
                    asm volatile("ldmatrix.sync.aligned.m8n8.x4.trans.shared.b16 {%0,%1,%2,%3}, [%4];\n"
                                 : "=r"(b0), "=r"(b1), "=r"(b2), "=r"(b3) : "r"(addr));
                }
#pragma unroll
                for (int mt = 0; mt < 4; ++mt) {
                    asm volatile("mma.sync.aligned.m16n8k16.row.col.f32.f16.f16.f32 "
                                 "{%0,%1,%2,%3},{%4,%5,%6,%7},{%8,%9},{%0,%1,%2,%3};\n"
                                 : "+f"(acc[mt][2*nt][0]), "+f"(acc[mt][2*nt][1]),
                                   "+f"(acc[mt][2*nt][2]), "+f"(acc[mt][2*nt][3])
                                 : "r"(af[mt][0]), "r"(af[mt][1]), "r"(af[mt][2]), "r"(af[mt][3]),
                                   "r"(b0), "r"(b1));
                    asm volatile("mma.sync.aligned.m16n8k16.row.col.f32.f16.f16.f32 "
                                 "{%0,%1,%2,%3},{%4,%5,%6,%7},{%8,%9},{%0,%1,%2,%3};\n"
                                 : "+f"(acc[mt][2*nt+1][0]), "+f"(acc[mt][2*nt+1][1]),
                                   "+f"(acc[mt][2*nt+1][2]), "+f"(acc[mt][2*nt+1][3])
                                 : "r"(af[mt][0]), "r"(af[mt][1]), "r"(af[mt][2]), "r"(af[mt][3]),
                                   "r"(b2), "r"(b3));
                }
            }
        }

        __syncthreads();   // all warps done with stage k's buffer
        if (k + 2 < K3)
            issue_tile_copies(k + 2, smem, bsel, indices, base, M, Nfeat, t);
    }

    // ---- epilogue: fp32 acc -> fp16 rounding (match reference) -> fp32 store ----
    {
        const int g  = lane >> 2;
        const int cc = (lane & 3) * 2;
#pragma unroll
        for (int mt = 0; mt < 4; ++mt) {
            const int row0 = base + wm * 64 + mt * 16 + g;
            const int row1 = row0 + 8;
#pragma unroll
            for (int nt8 = 0; nt8 < 4; ++nt8) {
                int col = wn * 32 + nt8 * 8 + cc;
                if (row0 < M) {
                    float2 v;
                    v.x = __half2float(__float2half_rn(acc[mt][nt8][0]));
                    v.y = __half2float(__float2half_rn(acc[mt][nt8][1]));
                    *(float2*)(out + (long long)row0 * COUT + col) = v;
                }
                if (row1 < M) {
                    float2 v;
                    v.x = __half2float(__float2half_rn(acc[mt][nt8][2]));
                    v.y = __half2float(__float2half_rn(acc[mt][nt8][3]));
                    *(float2*)(out + (long long)row1 * COUT + col) = v;
                }
            }
        }
    }
}

extern "C" void kernel_launch(void* const* d_in, const int* in_sizes, int n_in,
                              void* d_out, int out_size)
{
    const float* features = (const float*)d_in[0];
    const int*   indices  = (const int*)d_in[1];
    const float* weight   = (const float*)d_in[2];
    float*       out      = (float*)d_out;

    const int M     = out_size / COUT;       // 200000
    const int Nfeat = in_sizes[0] / CIN;     // 200000
    const int grid  = (M + M_TILE - 1) / M_TILE;   // 782

    // unconditional (no static guards): idempotent, capture-safe attribute set
    cudaFuncSetAttribute(spconv_mma_kernel,
                         cudaFuncAttributeMaxDynamicSharedMemorySize, SMEM_TOTAL);

    convert_kernel<<<1024, 256>>>(features, weight, Nfeat * CIN, K3 * CIN * COUT);
    spconv_mma_kernel<<<grid, NTHREADS, SMEM_TOTAL>>>(indices, out, M, Nfeat);
}